// round 16
// baseline (speedup 1.0000x reference)
#include <cuda_runtime.h>
#include <cuda_fp16.h>
#include <cstdint>
#include <cfloat>

#define NB  128
#define PTS 2048
#define CIN 256
#define NITEMS 1024                   // 128 scenes * 8 chunks of 256 pts

// ---- smem word (uint32) offsets ----
#define BH_W   0                      // W1 fp16: 17 k16-blocks * 2048 words (paired layout)
#define FB_W   34816                  // A fp16 operand, 2 bufs * 128 rows * 24 words
#define TL_W   40960                  // tail A fp16: 128 rows * 8 words
#define RED_W  41984                  // 1024 floats
#define SMEM_WORDS 43008
#define SMEM_BYTES (SMEM_WORDS * 4)   // 172032 B

__device__ float    g_part[NITEMS * 256];   // per-item column max (unique writer, no atomics)
__device__ uint32_t g_w1h[17 * 2048];       // W1 fp16 paired layout (incl. tail block 16)

__device__ __forceinline__ uint32_t smem_u32(const void* p) {
    uint32_t a;
    asm("{ .reg .u64 t; cvta.to.shared.u64 t, %1; cvt.u32.u64 %0, t; }" : "=r"(a) : "l"(p));
    return a;
}
#define CP16(dst, src) asm volatile("cp.async.cg.shared.global [%0], [%1], 16;" :: "r"(dst), "l"(src) : "memory")
#define CPC()   asm volatile("cp.async.commit_group;" ::: "memory")
#define CPW(n)  asm volatile("cp.async.wait_group %0;" :: "n"(n) : "memory")

#define MMA16(c, a, b)                                                          \
    asm volatile("mma.sync.aligned.m16n8k16.row.col.f32.f16.f16.f32 "           \
        "{%0,%1,%2,%3}, {%4,%5,%6,%7}, {%8,%9}, {%0,%1,%2,%3};\n"               \
        : "+f"((c)[0]), "+f"((c)[1]), "+f"((c)[2]), "+f"((c)[3])                \
        : "r"((a)[0]), "r"((a)[1]), "r"((a)[2]), "r"((a)[3]),                   \
          "r"((b).x), "r"((b).y))

// ==================== prep: W1 -> fp16 PAIRED layout ====================
// word addr within k16 block: q*128 + g*16 + tg*4 + r*2 + wlo
//   where n = q*16 + r*8 + g (column), word-in-perm wp = 2*tg + wlo,
//   k-pair of wp: kk0 = (wp&1) ? wp+7 : wp  (same perm as before).
__global__ __launch_bounds__(256, 8)
void prep_kernel(const float* __restrict__ W1) {
    const int d = blockIdx.x * 256 + threadIdx.x;     // word index 0..34815
    const int kb = d >> 11, dd = d & 2047;
    const int q = dd >> 7, rem = dd & 127;
    const int gg = rem >> 4, tg = (rem >> 2) & 3, r = (rem >> 1) & 1, wlo = dd & 1;
    const int n = q * 16 + r * 8 + gg;
    const int wp = tg * 2 + wlo;
    const int kk0 = (wp & 1) ? (wp + 7) : wp;
    const int k0 = kb * 16 + kk0, k1 = k0 + 1;
    const float v0 = (k0 < 259) ? W1[(size_t)k0 * 256 + n] : 0.f;
    const float v1 = (k1 < 259) ? W1[(size_t)k1 * 256 + n] : 0.f;
    half2 h = __floats2half2_rn(v0, v1);
    g_w1h[d] = *(const uint32_t*)&h;
}

// ==================== persistent pointconv: GEMM1(fp16 mma) + seg-max ====================
// Mainloop identical to the 146.1us structure except B fragments load as LDS.128 pairs.
__global__ __launch_bounds__(512, 1)
void pointconv_kernel(const float* __restrict__ pos, const float* __restrict__ feat, int nCTA)
{
    extern __shared__ uint32_t smw[];
    const uint32_t sb = smem_u32(smw);

    const int tid  = threadIdx.x;
    const int lane = tid & 31, warp = tid >> 5;
    const int wm = warp & 3, wn = warp >> 2;
    const int g  = lane >> 2, tg = lane & 3;
    const int c  = blockIdx.x;

    const int n_items = (c < NITEMS) ? ((NITEMS - 1 - c) / nCTA + 1) : 0;
    const int TS = n_items * 16;

    const int lrow = tid >> 2, lp = tid & 3;
    const int lstep = lp >> 1, lsub = lp & 1;
    const int lkoff = lstep * 16 + lsub * 4;

    // per-warp B base offset within a k16 block (words): + pi*128 per ni-pair
    const int boff = wn * 512 + g * 16 + tg * 4;

    float4 bufA, bufB;
    auto fetch = [&](int q) {
        if (q < TS) {
            const int item = c + (q >> 4) * nCTA, sub = q & 15;
            const int R = (item >> 3) * PTS + (item & 7) * 256 + ((sub >> 3) << 7);
            const float* s0 = feat + (size_t)(R + lrow) * CIN + (sub & 7) * 32 + lkoff;
            bufA = *(const float4*)s0;
            bufB = *(const float4*)(s0 + 8);
        }
    };
    auto store_fb = [&](int q) {
        half2 w0 = __floats2half2_rn(bufA.x, bufA.y);
        half2 w1 = __floats2half2_rn(bufB.x, bufB.y);
        half2 w2 = __floats2half2_rn(bufA.z, bufA.w);
        half2 w3 = __floats2half2_rn(bufB.z, bufB.w);
        uint4 v = make_uint4(*(uint32_t*)&w0, *(uint32_t*)&w1, *(uint32_t*)&w2, *(uint32_t*)&w3);
        *(uint4*)(smw + FB_W + (q & 1) * 3072 + lrow * 24 + lstep * 8 + lsub * 4) = v;
    };

    // ---- prologue ----
    {
        const uint32_t dW = sb + BH_W * 4;
#pragma unroll
        for (int j = 0; j < 17; j++) {
            int w = (tid + 512 * j) * 4;
            CP16(dW + (uint32_t)w * 4, g_w1h + w);
        }
        CPC();
    }
    fetch(0);
    if (TS > 0) store_fb(0);
    fetch(1);
    CPW(0);

    float acc[2][8][4], rmax[8][2];
#pragma unroll
    for (int ni = 0; ni < 8; ni++) { rmax[ni][0] = -FLT_MAX; rmax[ni][1] = -FLT_MAX; }

    for (int i = 0; i < TS; i++) {
        __syncthreads();
        if (i + 1 < TS) store_fb(i + 1);
        fetch(i + 2);

        const int item = c + (i >> 4) * nCTA, sub = i & 15;
        const int Rb = (item >> 3) * PTS + (item & 7) * 256 + ((sub >> 3) << 7);

        if ((i & 7) == 0) {
#pragma unroll
            for (int mi = 0; mi < 2; mi++)
#pragma unroll
                for (int ni = 0; ni < 8; ni++)
#pragma unroll
                    for (int j = 0; j < 4; j++) acc[mi][ni][j] = 0.f;
            if (tid < 128) {   // raw-pos tail rows; z (kk=2) lives in WORD 2 per perm layout
                const int gr = Rb + tid;
                half2 h0 = __floats2half2_rn(pos[gr * 3 + 0], pos[gr * 3 + 1]);
                half2 h1 = __floats2half2_rn(pos[gr * 3 + 2], 0.f);
                *(uint4*)(smw + TL_W + tid * 8) =
                    make_uint4(*(uint32_t*)&h0, 0u, *(uint32_t*)&h1, 0u);
                *(uint4*)(smw + TL_W + tid * 8 + 4) = make_uint4(0u, 0u, 0u, 0u);
            }
        }

        const uint32_t* fb = smw + FB_W + (i & 1) * 3072;
#pragma unroll
        for (int step = 0; step < 2; step++) {
            uint32_t a[2][4];
#pragma unroll
            for (int mi = 0; mi < 2; mi++) {
                const int R = wm * 32 + mi * 16 + g;
                uint2 x = *(const uint2*)(fb + R * 24 + step * 8 + 2 * tg);
                uint2 y = *(const uint2*)(fb + (R + 8) * 24 + step * 8 + 2 * tg);
                a[mi][0] = x.x; a[mi][1] = y.x; a[mi][2] = x.y; a[mi][3] = y.y;
            }
            const uint32_t* bh = smw + BH_W + ((i & 7) * 2 + step) * 2048 + boff;
#pragma unroll
            for (int pi = 0; pi < 4; pi++) {
                const uint4 v = *(const uint4*)(bh + pi * 128);
                const uint2 b0 = make_uint2(v.x, v.y);
                const uint2 b1 = make_uint2(v.z, v.w);
                MMA16(acc[0][2 * pi],     a[0], b0);
                MMA16(acc[1][2 * pi],     a[1], b0);
                MMA16(acc[0][2 * pi + 1], a[0], b1);
                MMA16(acc[1][2 * pi + 1], a[1], b1);
            }
        }

        if ((i & 7) == 7) {
            uint32_t a[2][4];
#pragma unroll
            for (int mi = 0; mi < 2; mi++) {
                const int R = wm * 32 + mi * 16 + g;
                uint2 x = *(const uint2*)(smw + TL_W + R * 8 + 2 * tg);
                uint2 y = *(const uint2*)(smw + TL_W + (R + 8) * 8 + 2 * tg);
                a[mi][0] = x.x; a[mi][1] = y.x; a[mi][2] = x.y; a[mi][3] = y.y;
            }
            const uint32_t* bh = smw + BH_W + 16 * 2048 + boff;
#pragma unroll
            for (int pi = 0; pi < 4; pi++) {
                const uint4 v = *(const uint4*)(bh + pi * 128);
                const uint2 b0 = make_uint2(v.x, v.y);
                const uint2 b1 = make_uint2(v.z, v.w);
                MMA16(acc[0][2 * pi],     a[0], b0);
                MMA16(acc[1][2 * pi],     a[1], b0);
                MMA16(acc[0][2 * pi + 1], a[0], b1);
                MMA16(acc[1][2 * pi + 1], a[1], b1);
            }
#pragma unroll
            for (int ni = 0; ni < 8; ni++)
#pragma unroll
                for (int p = 0; p < 2; p++)
                    rmax[ni][p] = fmaxf(rmax[ni][p],
                        fmaxf(fmaxf(acc[0][ni][p], acc[0][ni][p + 2]),
                              fmaxf(acc[1][ni][p], acc[1][ni][p + 2])));
        }

        if ((i & 15) == 15) {
#pragma unroll
            for (int off = 4; off < 32; off <<= 1)
#pragma unroll
                for (int ni = 0; ni < 8; ni++)
#pragma unroll
                    for (int p = 0; p < 2; p++)
                        rmax[ni][p] = fmaxf(rmax[ni][p],
                                            __shfl_xor_sync(0xffffffffu, rmax[ni][p], off));
            float* red = (float*)(smw + RED_W);
            if (lane < 4) {
#pragma unroll
                for (int ni = 0; ni < 8; ni++)
#pragma unroll
                    for (int p = 0; p < 2; p++)
                        red[wm * 256 + wn * 64 + ni * 8 + 2 * tg + p] = rmax[ni][p];
            }
            __syncthreads();
            if (tid < 256) {
                float v = fmaxf(fmaxf(red[tid], red[256 + tid]),
                                fmaxf(red[512 + tid], red[768 + tid]));
                g_part[item * 256 + tid] = v;
            }
#pragma unroll
            for (int ni = 0; ni < 8; ni++) { rmax[ni][0] = -FLT_MAX; rmax[ni][1] = -FLT_MAX; }
        }
    }
}

// ==================== head: 2 scenes/block, k split across 2 threads ====================
__global__ __launch_bounds__(512, 2)
void head_kernel(const float* __restrict__ pos, const float* __restrict__ W1,
                 const float* __restrict__ b1, const float* __restrict__ W2,
                 const float* __restrict__ b2, const float* __restrict__ noise,
                 float* __restrict__ out) {
    const int t = threadIdx.x;
    const int sbase = blockIdx.y * 2;
    __shared__ float ag[2 * 256];
    __shared__ float cw[2][8][3];
    __shared__ float pmu[512], psg[512];

    // centroid: 256 threads/scene, 8 pts (24 contiguous floats) each
    {
        const int sl = t >> 8, lt = t & 255;
        const float* p = pos + ((size_t)(sbase + sl) * PTS + (size_t)lt * 8) * 3;
        float s0 = 0.f, s1 = 0.f, s2 = 0.f;
#pragma unroll
        for (int j = 0; j < 6; j++) {
            const float4 f = *(const float4*)(p + j * 4);
            const int m = (4 * j) % 3;
            if (m == 0)      { s0 += f.x + f.w; s1 += f.y; s2 += f.z; }
            else if (m == 1) { s1 += f.x + f.w; s2 += f.y; s0 += f.z; }
            else             { s2 += f.x + f.w; s0 += f.y; s1 += f.z; }
        }
#pragma unroll
        for (int off = 16; off > 0; off >>= 1) {
            s0 += __shfl_xor_sync(0xffffffffu, s0, off);
            s1 += __shfl_xor_sync(0xffffffffu, s1, off);
            s2 += __shfl_xor_sync(0xffffffffu, s2, off);
        }
        if ((t & 31) == 0) {
            const int w = (t >> 5) & 7;
            cw[sl][w][0] = s0; cw[sl][w][1] = s1; cw[sl][w][2] = s2;
        }
    }
    __syncthreads();

    // 8-way chunk max, add (b1 - c@W1b), relu
    {
        const int sl = t >> 8, k = t & 255;
        float cx = 0.f, cy = 0.f, cz = 0.f;
#pragma unroll
        for (int w = 0; w < 8; w++) { cx += cw[sl][w][0]; cy += cw[sl][w][1]; cz += cw[sl][w][2]; }
        cx *= (1.f / PTS); cy *= (1.f / PTS); cz *= (1.f / PTS);
        const float* pp = g_part + ((size_t)(sbase + sl) * 8) * 256 + k;
        float f = pp[0];
#pragma unroll
        for (int it = 1; it < 8; it++) f = fmaxf(f, pp[it * 256]);
        const float dlt = b1[k] - (cx * W1[65536 + k] + cy * W1[65792 + k] + cz * W1[66048 + k]);
        ag[sl * 256 + k] = fmaxf(f + dlt, 0.f);
    }
    __syncthreads();

    // GEMM2: each (scene,col) split over kh = 0/1
    const int col = blockIdx.x * 128 + (t & 127);
    const int sl  = (t >> 7) & 1;
    const int kh  = t >> 8;
    const float* a = ag + sl * 256 + kh * 128;
    const float* w = W2 + (size_t)kh * 128 * 512;
    float amu = 0.f, asg = 0.f;
#pragma unroll 8
    for (int k = 0; k < 128; k++) {
        const float av = a[k];
        amu = fmaf(av, w[(size_t)k * 512 + col], amu);
        asg = fmaf(av, w[(size_t)k * 512 + col + 256], asg);
    }
    pmu[t] = amu; psg[t] = asg;
    __syncthreads();
    if (t < 256) {
        const int s = sbase + sl;
        float mu = pmu[t] + pmu[t + 256] + b2[col];
        float sr = psg[t] + psg[t + 256] + b2[col + 256];
        float sp = fmaxf(sr, 0.f) + log1pf(expf(-fabsf(sr)));
        out[s * 256 + col] = mu + (sp + 1e-4f) * noise[s * 256 + col];
    }
}

extern "C" void kernel_launch(void* const* d_in, const int* in_sizes, int n_in,
                              void* d_out, int out_size) {
    const float* pos     = (const float*)d_in[0];
    const float* feature = (const float*)d_in[1];
    // d_in[2] = batch: structurally i >> 11, never read
    const float* W1      = (const float*)d_in[3];
    const float* b1      = (const float*)d_in[4];
    const float* W2      = (const float*)d_in[5];
    const float* b2      = (const float*)d_in[6];
    const float* noise   = (const float*)d_in[7];
    float* out = (float*)d_out;

    int nsm = 148;
    if (cudaDeviceGetAttribute(&nsm, cudaDevAttrMultiProcessorCount, 0) != cudaSuccess || nsm < 1)
        nsm = 148;
    if (nsm > NITEMS) nsm = NITEMS;

    cudaFuncSetAttribute(pointconv_kernel,
                         cudaFuncAttributeMaxDynamicSharedMemorySize, SMEM_BYTES);

    prep_kernel<<<136, 256>>>(W1);
    pointconv_kernel<<<nsm, 512, SMEM_BYTES>>>(pos, feature, nsm);
    head_kernel<<<dim3(2, 64), 512>>>(pos, W1, b1, W2, b2, noise, out);
}

// round 17
// speedup vs baseline: 1.5354x; 1.5354x over previous
#include <cuda_runtime.h>
#include <cuda_fp16.h>
#include <cstdint>
#include <cfloat>

#define NB  128
#define PTS 2048
#define CIN 256
#define NITEMS 1024                   // 128 scenes * 8 chunks of 256 pts

// ---- smem word (uint32) offsets ----
#define BH_W   0                      // W1 fp16: 17 k16-blocks * 256 n * 8 words
#define FB_W   34816                  // A fp16 operand, 2 bufs * 128 rows * 24 words
#define TL_W   40960                  // tail A fp16: 128 rows * 8 words
#define RED_W  41984                  // 1024 floats
#define SMEM_WORDS 43008
#define SMEM_BYTES (SMEM_WORDS * 4)   // 172032 B

__device__ float    g_part[NITEMS * 256];   // per-item column max (unique writer, no atomics)
__device__ uint32_t g_w1h[17 * 2048];       // W1 fp16 perm layout (incl. tail block 16)

__device__ __forceinline__ uint32_t smem_u32(const void* p) {
    uint32_t a;
    asm("{ .reg .u64 t; cvta.to.shared.u64 t, %1; cvt.u32.u64 %0, t; }" : "=r"(a) : "l"(p));
    return a;
}
#define CP16(dst, src) asm volatile("cp.async.cg.shared.global [%0], [%1], 16;" :: "r"(dst), "l"(src) : "memory")
#define CPC()   asm volatile("cp.async.commit_group;" ::: "memory")
#define CPW(n)  asm volatile("cp.async.wait_group %0;" :: "n"(n) : "memory")

#define MMA16(c, a, b)                                                          \
    asm volatile("mma.sync.aligned.m16n8k16.row.col.f32.f16.f16.f32 "           \
        "{%0,%1,%2,%3}, {%4,%5,%6,%7}, {%8,%9}, {%0,%1,%2,%3};\n"               \
        : "+f"((c)[0]), "+f"((c)[1]), "+f"((c)[2]), "+f"((c)[3])                \
        : "r"((a)[0]), "r"((a)[1]), "r"((a)[2]), "r"((a)[3]),                   \
          "r"((b).x), "r"((b).y))

// ==================== prep: W1 -> fp16 perm layout (flat mapping) ====================
__global__ __launch_bounds__(256, 8)
void prep_kernel(const float* __restrict__ W1) {
    const int d = blockIdx.x * 256 + threadIdx.x;     // word index 0..34815
    const int kb = d >> 11, rem = d & 2047;
    const int n = rem >> 3, wp = rem & 7;
    const int kk0 = (wp & 1) ? (wp + 7) : wp;
    const int k0 = kb * 16 + kk0, k1 = k0 + 1;
    const float v0 = (k0 < 259) ? W1[(size_t)k0 * 256 + n] : 0.f;
    const float v1 = (k1 < 259) ? W1[(size_t)k1 * 256 + n] : 0.f;
    half2 h = __floats2half2_rn(v0, v1);
    g_w1h[d] = *(const uint32_t*)&h;
}

// ==================== persistent pointconv: GEMM1(fp16 mma) + seg-max ====================
// (the twice-measured 146.1us configuration)
__global__ __launch_bounds__(512, 1)
void pointconv_kernel(const float* __restrict__ pos, const float* __restrict__ feat, int nCTA)
{
    extern __shared__ uint32_t smw[];
    const uint32_t sb = smem_u32(smw);

    const int tid  = threadIdx.x;
    const int lane = tid & 31, warp = tid >> 5;
    const int wm = warp & 3, wn = warp >> 2;
    const int g  = lane >> 2, tg = lane & 3;
    const int c  = blockIdx.x;

    const int n_items = (c < NITEMS) ? ((NITEMS - 1 - c) / nCTA + 1) : 0;
    const int TS = n_items * 16;

    const int lrow = tid >> 2, lp = tid & 3;
    const int lstep = lp >> 1, lsub = lp & 1;
    const int lkoff = lstep * 16 + lsub * 4;

    float4 bufA, bufB;
    auto fetch = [&](int q) {
        if (q < TS) {
            const int item = c + (q >> 4) * nCTA, sub = q & 15;
            const int R = (item >> 3) * PTS + (item & 7) * 256 + ((sub >> 3) << 7);
            const float* s0 = feat + (size_t)(R + lrow) * CIN + (sub & 7) * 32 + lkoff;
            bufA = *(const float4*)s0;
            bufB = *(const float4*)(s0 + 8);
        }
    };
    auto store_fb = [&](int q) {
        half2 w0 = __floats2half2_rn(bufA.x, bufA.y);
        half2 w1 = __floats2half2_rn(bufB.x, bufB.y);
        half2 w2 = __floats2half2_rn(bufA.z, bufA.w);
        half2 w3 = __floats2half2_rn(bufB.z, bufB.w);
        uint4 v = make_uint4(*(uint32_t*)&w0, *(uint32_t*)&w1, *(uint32_t*)&w2, *(uint32_t*)&w3);
        *(uint4*)(smw + FB_W + (q & 1) * 3072 + lrow * 24 + lstep * 8 + lsub * 4) = v;
    };

    // ---- prologue ----
    {
        const uint32_t dW = sb + BH_W * 4;
#pragma unroll
        for (int j = 0; j < 17; j++) {
            int w = (tid + 512 * j) * 4;
            CP16(dW + (uint32_t)w * 4, g_w1h + w);
        }
        CPC();
    }
    fetch(0);
    if (TS > 0) store_fb(0);
    fetch(1);
    CPW(0);

    float acc[2][8][4], rmax[8][2];
#pragma unroll
    for (int ni = 0; ni < 8; ni++) { rmax[ni][0] = -FLT_MAX; rmax[ni][1] = -FLT_MAX; }

    for (int i = 0; i < TS; i++) {
        __syncthreads();
        if (i + 1 < TS) store_fb(i + 1);
        fetch(i + 2);

        const int item = c + (i >> 4) * nCTA, sub = i & 15;
        const int Rb = (item >> 3) * PTS + (item & 7) * 256 + ((sub >> 3) << 7);

        if ((i & 7) == 0) {
#pragma unroll
            for (int mi = 0; mi < 2; mi++)
#pragma unroll
                for (int ni = 0; ni < 8; ni++)
#pragma unroll
                    for (int j = 0; j < 4; j++) acc[mi][ni][j] = 0.f;
            if (tid < 128) {   // raw-pos tail rows; z (kk=2) lives in WORD 2 per perm layout
                const int gr = Rb + tid;
                half2 h0 = __floats2half2_rn(pos[gr * 3 + 0], pos[gr * 3 + 1]);
                half2 h1 = __floats2half2_rn(pos[gr * 3 + 2], 0.f);
                *(uint4*)(smw + TL_W + tid * 8) =
                    make_uint4(*(uint32_t*)&h0, 0u, *(uint32_t*)&h1, 0u);
                *(uint4*)(smw + TL_W + tid * 8 + 4) = make_uint4(0u, 0u, 0u, 0u);
            }
        }

        const uint32_t* fb = smw + FB_W + (i & 1) * 3072;
#pragma unroll
        for (int step = 0; step < 2; step++) {
            uint32_t a[2][4];
#pragma unroll
            for (int mi = 0; mi < 2; mi++) {
                const int R = wm * 32 + mi * 16 + g;
                uint2 x = *(const uint2*)(fb + R * 24 + step * 8 + 2 * tg);
                uint2 y = *(const uint2*)(fb + (R + 8) * 24 + step * 8 + 2 * tg);
                a[mi][0] = x.x; a[mi][1] = y.x; a[mi][2] = x.y; a[mi][3] = y.y;
            }
            const uint32_t* bh = smw + BH_W + ((i & 7) * 2 + step) * 2048;
#pragma unroll
            for (int ni = 0; ni < 8; ni++) {
                uint2 b = *(const uint2*)(bh + (wn * 64 + ni * 8 + g) * 8 + 2 * tg);
                MMA16(acc[0][ni], a[0], b);
                MMA16(acc[1][ni], a[1], b);
            }
        }

        if ((i & 7) == 7) {
            uint32_t a[2][4];
#pragma unroll
            for (int mi = 0; mi < 2; mi++) {
                const int R = wm * 32 + mi * 16 + g;
                uint2 x = *(const uint2*)(smw + TL_W + R * 8 + 2 * tg);
                uint2 y = *(const uint2*)(smw + TL_W + (R + 8) * 8 + 2 * tg);
                a[mi][0] = x.x; a[mi][1] = y.x; a[mi][2] = x.y; a[mi][3] = y.y;
            }
            const uint32_t* bh = smw + BH_W + 16 * 2048;
#pragma unroll
            for (int ni = 0; ni < 8; ni++) {
                uint2 b = *(const uint2*)(bh + (wn * 64 + ni * 8 + g) * 8 + 2 * tg);
                MMA16(acc[0][ni], a[0], b);
                MMA16(acc[1][ni], a[1], b);
            }
#pragma unroll
            for (int ni = 0; ni < 8; ni++)
#pragma unroll
                for (int p = 0; p < 2; p++)
                    rmax[ni][p] = fmaxf(rmax[ni][p],
                        fmaxf(fmaxf(acc[0][ni][p], acc[0][ni][p + 2]),
                              fmaxf(acc[1][ni][p], acc[1][ni][p + 2])));
        }

        if ((i & 15) == 15) {
#pragma unroll
            for (int off = 4; off < 32; off <<= 1)
#pragma unroll
                for (int ni = 0; ni < 8; ni++)
#pragma unroll
                    for (int p = 0; p < 2; p++)
                        rmax[ni][p] = fmaxf(rmax[ni][p],
                                            __shfl_xor_sync(0xffffffffu, rmax[ni][p], off));
            float* red = (float*)(smw + RED_W);
            if (lane < 4) {
#pragma unroll
                for (int ni = 0; ni < 8; ni++)
#pragma unroll
                    for (int p = 0; p < 2; p++)
                        red[wm * 256 + wn * 64 + ni * 8 + 2 * tg + p] = rmax[ni][p];
            }
            __syncthreads();
            if (tid < 256) {
                float v = fmaxf(fmaxf(red[tid], red[256 + tid]),
                                fmaxf(red[512 + tid], red[768 + tid]));
                g_part[item * 256 + tid] = v;
            }
#pragma unroll
            for (int ni = 0; ni < 8; ni++) { rmax[ni][0] = -FLT_MAX; rmax[ni][1] = -FLT_MAX; }
        }
    }
}

// ==================== head: 2 scenes/block, k split across 2 threads ====================
__global__ __launch_bounds__(512, 2)
void head_kernel(const float* __restrict__ pos, const float* __restrict__ W1,
                 const float* __restrict__ b1, const float* __restrict__ W2,
                 const float* __restrict__ b2, const float* __restrict__ noise,
                 float* __restrict__ out) {
    const int t = threadIdx.x;
    const int sbase = blockIdx.y * 2;
    __shared__ float ag[2 * 256];
    __shared__ float cw[2][8][3];
    __shared__ float pmu[512], psg[512];

    // centroid: 256 threads/scene, 8 pts (24 contiguous floats) each
    {
        const int sl = t >> 8, lt = t & 255;
        const float* p = pos + ((size_t)(sbase + sl) * PTS + (size_t)lt * 8) * 3;
        float s0 = 0.f, s1 = 0.f, s2 = 0.f;
#pragma unroll
        for (int j = 0; j < 6; j++) {
            const float4 f = *(const float4*)(p + j * 4);
            const int m = (4 * j) % 3;
            if (m == 0)      { s0 += f.x + f.w; s1 += f.y; s2 += f.z; }
            else if (m == 1) { s1 += f.x + f.w; s2 += f.y; s0 += f.z; }
            else             { s2 += f.x + f.w; s0 += f.y; s1 += f.z; }
        }
#pragma unroll
        for (int off = 16; off > 0; off >>= 1) {
            s0 += __shfl_xor_sync(0xffffffffu, s0, off);
            s1 += __shfl_xor_sync(0xffffffffu, s1, off);
            s2 += __shfl_xor_sync(0xffffffffu, s2, off);
        }
        if ((t & 31) == 0) {
            const int w = (t >> 5) & 7;
            cw[sl][w][0] = s0; cw[sl][w][1] = s1; cw[sl][w][2] = s2;
        }
    }
    __syncthreads();

    // 8-way chunk max, add (b1 - c@W1b), relu
    {
        const int sl = t >> 8, k = t & 255;
        float cx = 0.f, cy = 0.f, cz = 0.f;
#pragma unroll
        for (int w = 0; w < 8; w++) { cx += cw[sl][w][0]; cy += cw[sl][w][1]; cz += cw[sl][w][2]; }
        cx *= (1.f / PTS); cy *= (1.f / PTS); cz *= (1.f / PTS);
        const float* pp = g_part + ((size_t)(sbase + sl) * 8) * 256 + k;
        float f = pp[0];
#pragma unroll
        for (int it = 1; it < 8; it++) f = fmaxf(f, pp[it * 256]);
        const float dlt = b1[k] - (cx * W1[65536 + k] + cy * W1[65792 + k] + cz * W1[66048 + k]);
        ag[sl * 256 + k] = fmaxf(f + dlt, 0.f);
    }
    __syncthreads();

    // GEMM2: each (scene,col) split over kh = 0/1
    const int col = blockIdx.x * 128 + (t & 127);
    const int sl  = (t >> 7) & 1;
    const int kh  = t >> 8;
    const float* a = ag + sl * 256 + kh * 128;
    const float* w = W2 + (size_t)kh * 128 * 512;
    float amu = 0.f, asg = 0.f;
#pragma unroll 8
    for (int k = 0; k < 128; k++) {
        const float av = a[k];
        amu = fmaf(av, w[(size_t)k * 512 + col], amu);
        asg = fmaf(av, w[(size_t)k * 512 + col + 256], asg);
    }
    pmu[t] = amu; psg[t] = asg;
    __syncthreads();
    if (t < 256) {
        const int s = sbase + sl;
        float mu = pmu[t] + pmu[t + 256] + b2[col];
        float sr = psg[t] + psg[t + 256] + b2[col + 256];
        float sp = fmaxf(sr, 0.f) + log1pf(expf(-fabsf(sr)));
        out[s * 256 + col] = mu + (sp + 1e-4f) * noise[s * 256 + col];
    }
}

extern "C" void kernel_launch(void* const* d_in, const int* in_sizes, int n_in,
                              void* d_out, int out_size) {
    const float* pos     = (const float*)d_in[0];
    const float* feature = (const float*)d_in[1];
    // d_in[2] = batch: structurally i >> 11, never read
    const float* W1      = (const float*)d_in[3];
    const float* b1      = (const float*)d_in[4];
    const float* W2      = (const float*)d_in[5];
    const float* b2      = (const float*)d_in[6];
    const float* noise   = (const float*)d_in[7];
    float* out = (float*)d_out;

    int nsm = 148;
    if (cudaDeviceGetAttribute(&nsm, cudaDevAttrMultiProcessorCount, 0) != cudaSuccess || nsm < 1)
        nsm = 148;
    if (nsm > NITEMS) nsm = NITEMS;

    cudaFuncSetAttribute(pointconv_kernel,
                         cudaFuncAttributeMaxDynamicSharedMemorySize, SMEM_BYTES);

    prep_kernel<<<136, 256>>>(W1);
    pointconv_kernel<<<nsm, 512, SMEM_BYTES>>>(pos, feature, nsm);
    head_kernel<<<dim3(2, 64), 512>>>(pos, W1, b1, W2, b2, noise, out);
}